// round 2
// baseline (speedup 1.0000x reference)
#include <cuda_runtime.h>
#include <math.h>

#define SEQ 1024
#define HD 64
#define NUM_BH 64   // B*heads = 4*16
#define APAD 65

// Scratch: Q/K/V in [B*h, S, d] layout (16.8 MB each)
__device__ float g_q[NUM_BH * SEQ * HD];
__device__ float g_k[NUM_BH * SEQ * HD];
__device__ float g_v[NUM_BH * SEQ * HD];

// ---------------------------------------------------------------------------
// Kernel 1: QKV GEMM.  C[m,o] = sum_k A[m,k]*W[o,k] + bias[o]
// A = hidden [4096,1024], W = qkv_w [3072,1024] (K-major both).
// Scatter outputs directly into head-major g_q/g_k/g_v.
// 128x128 block tile, BK=16, 256 threads, 8x8 interleaved micro-tile.
// ---------------------------------------------------------------------------
__global__ __launch_bounds__(256) void qkv_gemm_kernel(
    const float* __restrict__ A, const float* __restrict__ W,
    const float* __restrict__ bias)
{
    __shared__ float As[16][132];
    __shared__ float Bs[16][132];

    const int m0 = blockIdx.y * 128;
    const int n0 = blockIdx.x * 128;
    const int tid = threadIdx.x;
    const int tx = tid & 15, ty = tid >> 4;

    float acc[8][8];
    #pragma unroll
    for (int i = 0; i < 8; i++)
        #pragma unroll
        for (int j = 0; j < 8; j++) acc[i][j] = 0.f;

    for (int k0 = 0; k0 < 1024; k0 += 16) {
        #pragma unroll
        for (int t = 0; t < 2; t++) {
            int idx = tid + t * 256;          // 512 float4 slots
            int row = idx >> 2;               // 0..127
            int c4  = (idx & 3) * 4;          // 0,4,8,12
            float4 va = *(const float4*)(A + (size_t)(m0 + row) * 1024 + k0 + c4);
            As[c4 + 0][row] = va.x;
            As[c4 + 1][row] = va.y;
            As[c4 + 2][row] = va.z;
            As[c4 + 3][row] = va.w;
            float4 vb = *(const float4*)(W + (size_t)(n0 + row) * 1024 + k0 + c4);
            Bs[c4 + 0][row] = vb.x;
            Bs[c4 + 1][row] = vb.y;
            Bs[c4 + 2][row] = vb.z;
            Bs[c4 + 3][row] = vb.w;
        }
        __syncthreads();
        #pragma unroll
        for (int kk = 0; kk < 16; kk++) {
            float a[8], b[8];
            #pragma unroll
            for (int i = 0; i < 8; i++) a[i] = As[kk][ty + 16 * i];
            #pragma unroll
            for (int j = 0; j < 8; j++) b[j] = Bs[kk][tx + 16 * j];
            #pragma unroll
            for (int i = 0; i < 8; i++)
                #pragma unroll
                for (int j = 0; j < 8; j++)
                    acc[i][j] = fmaf(a[i], b[j], acc[i][j]);
        }
        __syncthreads();
    }

    #pragma unroll
    for (int j = 0; j < 8; j++) {
        int o = n0 + tx + 16 * j;
        float bv = bias[o];
        int part = o >> 10;
        int oo = o & 1023;
        int head = oo >> 6, dd = oo & 63;
        float* dst = (part == 0) ? g_q : ((part == 1) ? g_k : g_v);
        #pragma unroll
        for (int i = 0; i < 8; i++) {
            int m = m0 + ty + 16 * i;
            int bb = m >> 10, s = m & 1023;
            dst[((size_t)(bb * 16 + head) * SEQ + s) * HD + dd] = acc[i][j] + bv;
        }
    }
}

// ---------------------------------------------------------------------------
// Kernel 2: fused relative-position attention, flash-style online softmax.
// One block = one (b,h) and a 64-row query tile. 256 threads, 4x4 interleaved.
// scores[l,r] = (q.k + q.pe + k.pe)/8 + mask[r],  pe row p = l-r+1023.
// Per 64x64 tile, p spans 127 consecutive dist_emb rows -> smem window.
// ---------------------------------------------------------------------------
__global__ __launch_bounds__(256) void attn_kernel(
    const float* __restrict__ dist_emb,
    const float* __restrict__ ext_mask,
    float* __restrict__ out)
{
    extern __shared__ float smem[];
    float* q_s  = smem;                 // 64*65
    float* k_s  = q_s  + 64 * APAD;
    float* v_s  = k_s  + 64 * APAD;
    float* p_s  = v_s  + 64 * APAD;
    float* de_s = p_s  + 64 * APAD;     // 127*65

    const int bh = blockIdx.y;
    const int l0 = blockIdx.x * 64;
    const int tid = threadIdx.x;
    const int tx = tid & 15, ty = tid >> 4;
    const int b = bh >> 4, h = bh & 15;

    const float* qg = g_q + (size_t)bh * SEQ * HD;
    const float* kg = g_k + (size_t)bh * SEQ * HD;
    const float* vg = g_v + (size_t)bh * SEQ * HD;
    const float* maskrow = ext_mask + (size_t)b * SEQ;

    // load Q tile (64x64 floats = 1024 float4)
    for (int t = tid; t < 1024; t += 256) {
        int row = t >> 4, c4 = (t & 15) * 4;
        float4 v4 = *(const float4*)(qg + (size_t)(l0 + row) * HD + c4);
        q_s[row * APAD + c4 + 0] = v4.x;
        q_s[row * APAD + c4 + 1] = v4.y;
        q_s[row * APAD + c4 + 2] = v4.z;
        q_s[row * APAD + c4 + 3] = v4.w;
    }

    float acc[4][4];
    float mrow[4], lrow[4];
    #pragma unroll
    for (int i = 0; i < 4; i++) {
        mrow[i] = -1e30f; lrow[i] = 0.f;
        #pragma unroll
        for (int j = 0; j < 4; j++) acc[i][j] = 0.f;
    }

    for (int r0 = 0; r0 < SEQ; r0 += 64) {
        // K / V tiles
        for (int t = tid; t < 1024; t += 256) {
            int row = t >> 4, c4 = (t & 15) * 4;
            float4 kv = *(const float4*)(kg + (size_t)(r0 + row) * HD + c4);
            k_s[row * APAD + c4 + 0] = kv.x;
            k_s[row * APAD + c4 + 1] = kv.y;
            k_s[row * APAD + c4 + 2] = kv.z;
            k_s[row * APAD + c4 + 3] = kv.w;
            float4 vv = *(const float4*)(vg + (size_t)(r0 + row) * HD + c4);
            v_s[row * APAD + c4 + 0] = vv.x;
            v_s[row * APAD + c4 + 1] = vv.y;
            v_s[row * APAD + c4 + 2] = vv.z;
            v_s[row * APAD + c4 + 3] = vv.w;
        }
        // dist_emb window: rows [pmin, pmin+126], pmin = l0-r0+960 in [0,1920]
        {
            int pmin = l0 - r0 + 960;
            for (int t = tid; t < 2032; t += 256) {   // 127*16 float4
                int row = t >> 4, c4 = (t & 15) * 4;
                float4 dv = *(const float4*)(dist_emb + (size_t)(pmin + row) * HD + c4);
                de_s[row * APAD + c4 + 0] = dv.x;
                de_s[row * APAD + c4 + 1] = dv.y;
                de_s[row * APAD + c4 + 2] = dv.z;
                de_s[row * APAD + c4 + 3] = dv.w;
            }
        }
        __syncthreads();

        // ---- score tile: s[i][j] for l = l0+ty+16i, r = r0+tx+16j ----
        float s[4][4];
        #pragma unroll
        for (int i = 0; i < 4; i++)
            #pragma unroll
            for (int j = 0; j < 4; j++) s[i][j] = 0.f;

        const int dbase = (ty - tx + 15) * APAD;   // t-th diagonal at +16*t*APAD
        #pragma unroll 4
        for (int dk = 0; dk < 64; dk++) {
            float a[4], kb[4], d7[7];
            #pragma unroll
            for (int i = 0; i < 4; i++) a[i] = q_s[(ty + 16 * i) * APAD + dk];
            #pragma unroll
            for (int j = 0; j < 4; j++) kb[j] = k_s[(tx + 16 * j) * APAD + dk];
            #pragma unroll
            for (int t = 0; t < 7; t++) d7[t] = de_s[dbase + t * 16 * APAD + dk];
            #pragma unroll
            for (int i = 0; i < 4; i++)
                #pragma unroll
                for (int j = 0; j < 4; j++) {
                    float dd = d7[i - j + 3];
                    s[i][j] = fmaf(a[i], kb[j], s[i][j]);
                    s[i][j] = fmaf(a[i] + kb[j], dd, s[i][j]);
                }
        }

        float mk[4];
        #pragma unroll
        for (int j = 0; j < 4; j++) mk[j] = maskrow[r0 + tx + 16 * j];
        #pragma unroll
        for (int i = 0; i < 4; i++)
            #pragma unroll
            for (int j = 0; j < 4; j++)
                s[i][j] = s[i][j] * 0.125f + mk[j];

        // ---- online softmax (row stats via half-warp shuffles) ----
        #pragma unroll
        for (int i = 0; i < 4; i++) {
            float tm = fmaxf(fmaxf(s[i][0], s[i][1]), fmaxf(s[i][2], s[i][3]));
            #pragma unroll
            for (int o = 8; o > 0; o >>= 1)
                tm = fmaxf(tm, __shfl_xor_sync(0xffffffffu, tm, o));
            float mnew = fmaxf(mrow[i], tm);
            float corr = __expf(mrow[i] - mnew);
            float psum = 0.f;
            #pragma unroll
            for (int j = 0; j < 4; j++) {
                s[i][j] = __expf(s[i][j] - mnew);
                psum += s[i][j];
            }
            #pragma unroll
            for (int o = 8; o > 0; o >>= 1)
                psum += __shfl_xor_sync(0xffffffffu, psum, o);
            lrow[i] = lrow[i] * corr + psum;
            mrow[i] = mnew;
            #pragma unroll
            for (int j = 0; j < 4; j++) acc[i][j] *= corr;
            #pragma unroll
            for (int j = 0; j < 4; j++)
                p_s[(ty + 16 * i) * APAD + tx + 16 * j] = s[i][j];
        }
        __syncthreads();

        // ---- ctx: acc[i][j] += sum_r p[l,r] * v[r, dd] ----
        #pragma unroll 4
        for (int r = 0; r < 64; r++) {
            float pv[4], vv[4];
            #pragma unroll
            for (int i = 0; i < 4; i++) pv[i] = p_s[(ty + 16 * i) * APAD + r];
            #pragma unroll
            for (int j = 0; j < 4; j++) vv[j] = v_s[r * APAD + tx + 16 * j];
            #pragma unroll
            for (int i = 0; i < 4; i++)
                #pragma unroll
                for (int j = 0; j < 4; j++)
                    acc[i][j] = fmaf(pv[i], vv[j], acc[i][j]);
        }
        __syncthreads();
    }

    // epilogue: out[b, l, h*64+dd] = acc / lsum
    #pragma unroll
    for (int i = 0; i < 4; i++) {
        float inv = 1.f / lrow[i];
        int l = l0 + ty + 16 * i;
        #pragma unroll
        for (int j = 0; j < 4; j++) {
            int dd = tx + 16 * j;
            out[((size_t)(b * SEQ + l) * 1024) + h * 64 + dd] = acc[i][j] * inv;
        }
    }
}

extern "C" void kernel_launch(void* const* d_in, const int* in_sizes, int n_in,
                              void* d_out, int out_size)
{
    const float* hidden   = (const float*)d_in[0];  // [4,1024,1024]
    const float* qkv_w    = (const float*)d_in[1];  // [3072,1024]
    const float* qkv_b    = (const float*)d_in[2];  // [3072]
    const float* dist_emb = (const float*)d_in[3];  // [2047,64]
    const float* ext_mask = (const float*)d_in[4];  // [4,1,1,1024]
    float* out = (float*)d_out;

    const int smem_bytes = (4 * 64 * APAD + 127 * APAD) * sizeof(float); // ~99.6 KB
    cudaFuncSetAttribute(attn_kernel,
                         cudaFuncAttributeMaxDynamicSharedMemorySize, smem_bytes);

    qkv_gemm_kernel<<<dim3(24, 32), 256>>>(hidden, qkv_w, qkv_b);
    attn_kernel<<<dim3(16, NUM_BH), 256, smem_bytes>>>(dist_emb, ext_mask, out);
}

// round 4
// speedup vs baseline: 1.3566x; 1.3566x over previous
#include <cuda_runtime.h>
#include <cuda_bf16.h>
#include <cstdint>
#include <math.h>

#define SEQ 1024
#define HD 64
#define NUM_BH 64
#define APAD 65

// Scratch
__device__ float g_q[NUM_BH * SEQ * HD];
__device__ float g_k[NUM_BH * SEQ * HD];
__device__ float g_v[NUM_BH * SEQ * HD];
// bf16 hi/lo splits
__device__ __nv_bfloat16 g_ah[4096 * 1024];
__device__ __nv_bfloat16 g_al[4096 * 1024];
__device__ __nv_bfloat16 g_wh[3072 * 1024];
__device__ __nv_bfloat16 g_wl[3072 * 1024];

// ---------------------------------------------------------------------------
// Kernel 0: split fp32 -> bf16 hi + lo
// ---------------------------------------------------------------------------
__global__ __launch_bounds__(256) void split_kernel(
    const float* __restrict__ hidden, const float* __restrict__ qkv_w)
{
    const int idx = blockIdx.x * 256 + threadIdx.x;   // float4 index
    const int A4 = 4096 * 1024 / 4;                   // 1048576
    const int T4 = A4 + 3072 * 1024 / 4;              // 1835008
    if (idx >= T4) return;
    const float4 v = (idx < A4) ? ((const float4*)hidden)[idx]
                                : ((const float4*)qkv_w)[idx - A4];
    __nv_bfloat16 h0 = __float2bfloat16_rn(v.x);
    __nv_bfloat16 h1 = __float2bfloat16_rn(v.y);
    __nv_bfloat16 h2 = __float2bfloat16_rn(v.z);
    __nv_bfloat16 h3 = __float2bfloat16_rn(v.w);
    __nv_bfloat16 l0 = __float2bfloat16_rn(v.x - __bfloat162float(h0));
    __nv_bfloat16 l1 = __float2bfloat16_rn(v.y - __bfloat162float(h1));
    __nv_bfloat16 l2 = __float2bfloat16_rn(v.z - __bfloat162float(h2));
    __nv_bfloat16 l3 = __float2bfloat16_rn(v.w - __bfloat162float(h3));
    __nv_bfloat162 hh0 = __nv_bfloat162(h0, h1), hh1 = __nv_bfloat162(h2, h3);
    __nv_bfloat162 ll0 = __nv_bfloat162(l0, l1), ll1 = __nv_bfloat162(l2, l3);
    if (idx < A4) {
        ((__nv_bfloat162*)g_ah)[2 * idx] = hh0; ((__nv_bfloat162*)g_ah)[2 * idx + 1] = hh1;
        ((__nv_bfloat162*)g_al)[2 * idx] = ll0; ((__nv_bfloat162*)g_al)[2 * idx + 1] = ll1;
    } else {
        int j = idx - A4;
        ((__nv_bfloat162*)g_wh)[2 * j] = hh0; ((__nv_bfloat162*)g_wh)[2 * j + 1] = hh1;
        ((__nv_bfloat162*)g_wl)[2 * j] = ll0; ((__nv_bfloat162*)g_wl)[2 * j + 1] = ll1;
    }
}

// ---------------------------------------------------------------------------
// Kernel 1: QKV GEMM via mma.sync bf16x3.
//   C[m,o] = sum_k A[m,k]*W[o,k] + bias[o], scatter head-major.
//   128x128 CTA tile, 8 warps (64x32 each), k-chunk 32, 3-stage cp.async.
// ---------------------------------------------------------------------------
#define PITCH 80                     // bytes per smem row (40 bf16)
#define TILE_B (128 * PITCH)         // 10240
#define STAGE_B (4 * TILE_B)         // Ah,Al,Wh,Wl
#define NST 3
#define NCHUNK 32

__device__ __forceinline__ uint32_t smem_u32(const void* p) {
    uint32_t a;
    asm("{ .reg .u64 t; cvta.to.shared.u64 t, %1; cvt.u32.u64 %0, t; }" : "=r"(a) : "l"(p));
    return a;
}
__device__ __forceinline__ void cp16(uint32_t dst, const void* src) {
    asm volatile("cp.async.cg.shared.global [%0], [%1], 16;" :: "r"(dst), "l"(src) : "memory");
}
#define CP_COMMIT() asm volatile("cp.async.commit_group;" ::: "memory")
#define CP_WAIT2()  asm volatile("cp.async.wait_group 2;" ::: "memory")

__device__ __forceinline__ void ldsm4(uint32_t& r0, uint32_t& r1, uint32_t& r2, uint32_t& r3,
                                      uint32_t addr) {
    asm volatile("ldmatrix.sync.aligned.m8n8.x4.shared.b16 {%0,%1,%2,%3}, [%4];"
                 : "=r"(r0), "=r"(r1), "=r"(r2), "=r"(r3) : "r"(addr));
}
__device__ __forceinline__ void mma16816(float* c, const uint32_t* a, uint32_t b0, uint32_t b1) {
    asm volatile(
        "mma.sync.aligned.m16n8k16.row.col.f32.bf16.bf16.f32 "
        "{%0,%1,%2,%3}, {%4,%5,%6,%7}, {%8,%9}, {%0,%1,%2,%3};"
        : "+f"(c[0]), "+f"(c[1]), "+f"(c[2]), "+f"(c[3])
        : "r"(a[0]), "r"(a[1]), "r"(a[2]), "r"(a[3]), "r"(b0), "r"(b1));
}

__global__ __launch_bounds__(256, 1) void qkv_mma_kernel(const float* __restrict__ bias)
{
    extern __shared__ __align__(128) char smem[];
    const uint32_t sb = smem_u32(smem);
    const int tid = threadIdx.x;
    const int wid = tid >> 5, lane = tid & 31;
    const int m0 = blockIdx.y * 128;
    const int n0 = blockIdx.x * 128;
    const int warp_m0 = (wid >> 2) * 64;
    const int warp_n0 = (wid & 3) * 32;

    // stage load: 2048 x 16B chunks (Ah,Al,Wh,Wl x 512)
    auto load_stage = [&](int c, int st) {
        const uint32_t sbase = sb + st * STAGE_B;
        #pragma unroll
        for (int t = 0; t < 8; t++) {
            int u = tid + t * 256;
            int tile = u >> 9;          // 0..3
            int w = u & 511;
            int row = w >> 2, ch = w & 3;
            uint32_t dst = sbase + tile * TILE_B + row * PITCH + ch * 16;
            const char* src;
            size_t off = (size_t)row * 2048 + (size_t)c * 64 + ch * 16;
            if (tile == 0)      src = (const char*)g_ah + (size_t)m0 * 2048 + off;
            else if (tile == 1) src = (const char*)g_al + (size_t)m0 * 2048 + off;
            else if (tile == 2) src = (const char*)g_wh + (size_t)n0 * 2048 + off;
            else                src = (const char*)g_wl + (size_t)n0 * 2048 + off;
            cp16(dst, src);
        }
    };

    float acc[4][4][4];
    #pragma unroll
    for (int i = 0; i < 4; i++)
        #pragma unroll
        for (int j = 0; j < 4; j++)
            #pragma unroll
            for (int t = 0; t < 4; t++) acc[i][j][t] = 0.f;

    load_stage(0, 0); CP_COMMIT();
    load_stage(1, 1); CP_COMMIT();
    load_stage(2, 2); CP_COMMIT();

    const uint32_t lrow = lane & 15, lhalf = lane >> 4;
    const uint32_t fragoff = lrow * PITCH + lhalf * 16;

    for (int c = 0; c < NCHUNK; c++) {
        CP_WAIT2();
        __syncthreads();
        const uint32_t sbase = sb + (c % NST) * STAGE_B;
        const uint32_t sAh = sbase;
        const uint32_t sAl = sbase + TILE_B;
        const uint32_t sWh = sbase + 2 * TILE_B;
        const uint32_t sWl = sbase + 3 * TILE_B;

        #pragma unroll
        for (int kk = 0; kk < 2; kk++) {
            const uint32_t ko = kk * 32;
            uint32_t ah[4][4], al[4][4], bh[2][4], bl[2][4];
            #pragma unroll
            for (int mt = 0; mt < 4; mt++) {
                uint32_t r = (warp_m0 + mt * 16) * PITCH + fragoff + ko;
                ldsm4(ah[mt][0], ah[mt][1], ah[mt][2], ah[mt][3], sAh + r);
                ldsm4(al[mt][0], al[mt][1], al[mt][2], al[mt][3], sAl + r);
            }
            #pragma unroll
            for (int nt = 0; nt < 2; nt++) {
                uint32_t r = (warp_n0 + nt * 16) * PITCH + fragoff + ko;
                ldsm4(bh[nt][0], bh[nt][1], bh[nt][2], bh[nt][3], sWh + r);
                ldsm4(bl[nt][0], bl[nt][1], bl[nt][2], bl[nt][3], sWl + r);
            }
            #pragma unroll
            for (int mt = 0; mt < 4; mt++)
                #pragma unroll
                for (int nt = 0; nt < 4; nt++) {
                    const int n16 = nt >> 1, sel = nt & 1;
                    mma16816(acc[mt][nt], ah[mt], bh[n16][sel], bh[n16][sel + 2]);
                    mma16816(acc[mt][nt], ah[mt], bl[n16][sel], bl[n16][sel + 2]);
                    mma16816(acc[mt][nt], al[mt], bh[n16][sel], bh[n16][sel + 2]);
                }
        }
        __syncthreads();
        if (c + 3 < NCHUNK) load_stage(c + 3, (c + 3) % NST);
        CP_COMMIT();
    }

    // epilogue: scatter with bias into head-major g_q/g_k/g_v
    #pragma unroll
    for (int nt = 0; nt < 4; nt++) {
        const int o = n0 + warp_n0 + nt * 8 + 2 * (lane & 3);
        const float2 bv = *(const float2*)(bias + o);
        const int part = o >> 10;
        const int oo = o & 1023;
        const int head = oo >> 6, dd = oo & 63;
        float* dst = (part == 0) ? g_q : ((part == 1) ? g_k : g_v);
        #pragma unroll
        for (int mt = 0; mt < 4; mt++) {
            const int m = m0 + warp_m0 + mt * 16 + (lane >> 2);
            const int bb = m >> 10, s = m & 1023;
            float* p0 = dst + ((size_t)(bb * 16 + head) * SEQ + s) * HD + dd;
            float2 v0 = make_float2(acc[mt][nt][0] + bv.x, acc[mt][nt][1] + bv.y);
            *(float2*)p0 = v0;
            float* p1 = dst + ((size_t)(bb * 16 + head) * SEQ + (s + 8)) * HD + dd;
            float2 v1 = make_float2(acc[mt][nt][2] + bv.x, acc[mt][nt][3] + bv.y);
            *(float2*)p1 = v1;
        }
    }
}

// ---------------------------------------------------------------------------
// Kernel 2: fused relative-position attention (unchanged, known-good R2)
// ---------------------------------------------------------------------------
__global__ __launch_bounds__(256) void attn_kernel(
    const float* __restrict__ dist_emb,
    const float* __restrict__ ext_mask,
    float* __restrict__ out)
{
    extern __shared__ float smemf[];
    float* q_s  = smemf;
    float* k_s  = q_s  + 64 * APAD;
    float* v_s  = k_s  + 64 * APAD;
    float* p_s  = v_s  + 64 * APAD;
    float* de_s = p_s  + 64 * APAD;

    const int bh = blockIdx.y;
    const int l0 = blockIdx.x * 64;
    const int tid = threadIdx.x;
    const int tx = tid & 15, ty = tid >> 4;
    const int b = bh >> 4, h = bh & 15;

    const float* qg = g_q + (size_t)bh * SEQ * HD;
    const float* kg = g_k + (size_t)bh * SEQ * HD;
    const float* vg = g_v + (size_t)bh * SEQ * HD;
    const float* maskrow = ext_mask + (size_t)b * SEQ;

    for (int t = tid; t < 1024; t += 256) {
        int row = t >> 4, c4 = (t & 15) * 4;
        float4 v4 = *(const float4*)(qg + (size_t)(l0 + row) * HD + c4);
        q_s[row * APAD + c4 + 0] = v4.x;
        q_s[row * APAD + c4 + 1] = v4.y;
        q_s[row * APAD + c4 + 2] = v4.z;
        q_s[row * APAD + c4 + 3] = v4.w;
    }

    float acc[4][4];
    float mrow[4], lrow[4];
    #pragma unroll
    for (int i = 0; i < 4; i++) {
        mrow[i] = -1e30f; lrow[i] = 0.f;
        #pragma unroll
        for (int j = 0; j < 4; j++) acc[i][j] = 0.f;
    }

    for (int r0 = 0; r0 < SEQ; r0 += 64) {
        for (int t = tid; t < 1024; t += 256) {
            int row = t >> 4, c4 = (t & 15) * 4;
            float4 kv = *(const float4*)(kg + (size_t)(r0 + row) * HD + c4);
            k_s[row * APAD + c4 + 0] = kv.x;
            k_s[row * APAD + c4 + 1] = kv.y;
            k_s[row * APAD + c4 + 2] = kv.z;
            k_s[row * APAD + c4 + 3] = kv.w;
            float4 vv = *(const float4*)(vg + (size_t)(r0 + row) * HD + c4);
            v_s[row * APAD + c4 + 0] = vv.x;
            v_s[row * APAD + c4 + 1] = vv.y;
            v_s[row * APAD + c4 + 2] = vv.z;
            v_s[row * APAD + c4 + 3] = vv.w;
        }
        {
            int pmin = l0 - r0 + 960;
            for (int t = tid; t < 2032; t += 256) {
                int row = t >> 4, c4 = (t & 15) * 4;
                float4 dv = *(const float4*)(dist_emb + (size_t)(pmin + row) * HD + c4);
                de_s[row * APAD + c4 + 0] = dv.x;
                de_s[row * APAD + c4 + 1] = dv.y;
                de_s[row * APAD + c4 + 2] = dv.z;
                de_s[row * APAD + c4 + 3] = dv.w;
            }
        }
        __syncthreads();

        float s[4][4];
        #pragma unroll
        for (int i = 0; i < 4; i++)
            #pragma unroll
            for (int j = 0; j < 4; j++) s[i][j] = 0.f;

        const int dbase = (ty - tx + 15) * APAD;
        #pragma unroll 4
        for (int dk = 0; dk < 64; dk++) {
            float a[4], kb[4], d7[7];
            #pragma unroll
            for (int i = 0; i < 4; i++) a[i] = q_s[(ty + 16 * i) * APAD + dk];
            #pragma unroll
            for (int j = 0; j < 4; j++) kb[j] = k_s[(tx + 16 * j) * APAD + dk];
            #pragma unroll
            for (int t = 0; t < 7; t++) d7[t] = de_s[dbase + t * 16 * APAD + dk];
            #pragma unroll
            for (int i = 0; i < 4; i++)
                #pragma unroll
                for (int j = 0; j < 4; j++) {
                    float dd = d7[i - j + 3];
                    s[i][j] = fmaf(a[i], kb[j], s[i][j]);
                    s[i][j] = fmaf(a[i] + kb[j], dd, s[i][j]);
                }
        }

        float mk[4];
        #pragma unroll
        for (int j = 0; j < 4; j++) mk[j] = maskrow[r0 + tx + 16 * j];
        #pragma unroll
        for (int i = 0; i < 4; i++)
            #pragma unroll
            for (int j = 0; j < 4; j++)
                s[i][j] = s[i][j] * 0.125f + mk[j];

        #pragma unroll
        for (int i = 0; i < 4; i++) {
            float tm = fmaxf(fmaxf(s[i][0], s[i][1]), fmaxf(s[i][2], s[i][3]));
            #pragma unroll
            for (int o = 8; o > 0; o >>= 1)
                tm = fmaxf(tm, __shfl_xor_sync(0xffffffffu, tm, o));
            float mnew = fmaxf(mrow[i], tm);
            float corr = __expf(mrow[i] - mnew);
            float psum = 0.f;
            #pragma unroll
            for (int j = 0; j < 4; j++) {
                s[i][j] = __expf(s[i][j] - mnew);
                psum += s[i][j];
            }
            #pragma unroll
            for (int o = 8; o > 0; o >>= 1)
                psum += __shfl_xor_sync(0xffffffffu, psum, o);
            lrow[i] = lrow[i] * corr + psum;
            mrow[i] = mnew;
            #pragma unroll
            for (int j = 0; j < 4; j++) acc[i][j] *= corr;
            #pragma unroll
            for (int j = 0; j < 4; j++)
                p_s[(ty + 16 * i) * APAD + tx + 16 * j] = s[i][j];
        }
        __syncthreads();

        #pragma unroll 4
        for (int r = 0; r < 64; r++) {
            float pv[4], vv[4];
            #pragma unroll
            for (int i = 0; i < 4; i++) pv[i] = p_s[(ty + 16 * i) * APAD + r];
            #pragma unroll
            for (int j = 0; j < 4; j++) vv[j] = v_s[r * APAD + tx + 16 * j];
            #pragma unroll
            for (int i = 0; i < 4; i++)
                #pragma unroll
                for (int j = 0; j < 4; j++)
                    acc[i][j] = fmaf(pv[i], vv[j], acc[i][j]);
        }
        __syncthreads();
    }

    #pragma unroll
    for (int i = 0; i < 4; i++) {
        float inv = 1.f / lrow[i];
        int l = l0 + ty + 16 * i;
        #pragma unroll
        for (int j = 0; j < 4; j++) {
            int dd = tx + 16 * j;
            out[((size_t)(b * SEQ + l) * 1024) + h * 64 + dd] = acc[i][j] * inv;
        }
    }
}

extern "C" void kernel_launch(void* const* d_in, const int* in_sizes, int n_in,
                              void* d_out, int out_size)
{
    const float* hidden   = (const float*)d_in[0];
    const float* qkv_w    = (const float*)d_in[1];
    const float* qkv_b    = (const float*)d_in[2];
    const float* dist_emb = (const float*)d_in[3];
    const float* ext_mask = (const float*)d_in[4];
    float* out = (float*)d_out;

    const int gemm_smem = NST * STAGE_B;   // 122880
    cudaFuncSetAttribute(qkv_mma_kernel,
                         cudaFuncAttributeMaxDynamicSharedMemorySize, gemm_smem);
    const int attn_smem = (4 * 64 * APAD + 127 * APAD) * sizeof(float);
    cudaFuncSetAttribute(attn_kernel,
                         cudaFuncAttributeMaxDynamicSharedMemorySize, attn_smem);

    split_kernel<<<(1835008 + 255) / 256, 256>>>(hidden, qkv_w);
    qkv_mma_kernel<<<dim3(3072 / 128, 4096 / 128), 256, gemm_smem>>>(qkv_b);
    attn_kernel<<<dim3(16, NUM_BH), 256, attn_smem>>>(dist_emb, ext_mask, out);
}